// round 6
// baseline (speedup 1.0000x reference)
#include <cuda_runtime.h>
#include <stdint.h>

#define N_BOX 32768
#define C_CLS 81
#define K_TOP 4096
#define SCORE_T 0.05f
#define NMS_T 0.5f
#define IMG_W 1333.0f
#define IMG_H 800.0f
#define CLS_OFF 4096.0f

#define CAND_MAX (N_BOX * 20)   // provably <=19 candidates/row (probs sum to 1)
#define SEL_MAX 16384

__device__ unsigned long long g_cand[CAND_MAX];
__device__ int g_cnt;
__device__ unsigned int g_hist[65536];
__device__ int g_cutBucket;
__device__ unsigned long long g_sel[SEL_MAX];
__device__ int g_selCnt;

__device__ float g_bk[K_TOP][4];
__device__ float g_boff[K_TOP][4];
__device__ float g_area[K_TOP];
__device__ float g_val[K_TOP];
__device__ int   g_label[K_TOP];

__device__ unsigned long long g_mask[K_TOP * 64];  // suppression bitmatrix
__device__ unsigned long long g_rowAny[64];
__device__ unsigned long long g_removed[64];

// xor-butterfly tree sum over the warp — all lanes end with identical bits
__device__ __forceinline__ float btree_add(float v) {
    #pragma unroll
    for (int o = 16; o; o >>= 1) v = __fadd_rn(v, __shfl_xor_sync(0xFFFFFFFFu, v, o));
    return v;
}

__global__ void k_zero() {
    int t = blockIdx.x * blockDim.x + threadIdx.x;
    if (t < 65536) g_hist[t] = 0u;
    if (t < 64)    g_rowAny[t] = 0ull;
    if (t == 0) { g_cnt = 0; g_selCnt = 0; }
}

// one warp per row — bitwise model of the Triton/MLIR normalization emitter:
// BLOCK=128 padded row, butterfly tree per contiguous 32-block, cross-warp
// butterfly combine => s = (B0 + B2) + B1; libdevice expf; div.rn.
__global__ void k_softmax(const float* __restrict__ x) {
    int warp = (blockIdx.x * blockDim.x + threadIdx.x) >> 5;
    int lane = threadIdx.x & 31;
    if (warp >= N_BOX) return;
    const float* row = x + (size_t)warp * C_CLS;

    float v0 = row[lane];
    float v1 = row[lane + 32];
    float v2 = (lane < 17) ? row[lane + 64] : -1e30f;

    float m = fmaxf(fmaxf(v0, v1), v2);   // max is order-exact
    #pragma unroll
    for (int o = 16; o; o >>= 1) m = fmaxf(m, __shfl_xor_sync(0xFFFFFFFFu, m, o));

    float e0 = expf(__fsub_rn(v0, m));
    float e1 = expf(__fsub_rn(v1, m));
    float e2 = (lane < 17) ? expf(__fsub_rn(v2, m)) : 0.0f;

    // contiguous-block butterfly trees, then (B0 + B2) + B1
    float B0 = btree_add(e0);
    float B1 = btree_add(e1);
    float B2 = btree_add(e2);
    float s = __fadd_rn(__fadd_rn(B0, B2), B1);

    float p[3];
    p[0] = __fdiv_rn(e0, s); p[1] = __fdiv_rn(e1, s); p[2] = __fdiv_rn(e2, s);

    #pragma unroll
    for (int k = 0; k < 3; k++) {
        int c = lane + 32 * k;
        bool valid = (c != 0) && (c < C_CLS) && (p[k] > SCORE_T);
        unsigned bal = __ballot_sync(0xFFFFFFFFu, valid);
        int nsel = __popc(bal);
        int base = 0;
        if (lane == 0 && nsel) base = atomicAdd(&g_cnt, nsel);
        base = __shfl_sync(0xFFFFFFFFu, base, 0);
        if (valid) {
            unsigned vb = __float_as_uint(p[k]);
            int pos = base + __popc(bal & ((1u << lane) - 1u));
            unsigned idx = (unsigned)warp * C_CLS + (unsigned)c;
            g_cand[pos] = ((unsigned long long)vb << 32) | (0xFFFFFFFFu - idx);
            atomicAdd(&g_hist[vb >> 16], 1u);
        }
    }
}

__global__ void k_findcut() {
    __shared__ unsigned int csum[256];
    int t = threadIdx.x;
    unsigned int s = 0;
    #pragma unroll 8
    for (int i = 0; i < 256; i++) s += g_hist[t * 256 + i];
    csum[t] = s;
    __syncthreads();
    if (t == 0) {
        unsigned int acc = 0;
        int ch = 255;
        for (; ch >= 0; ch--) {
            if (acc + csum[ch] >= K_TOP) break;
            acc += csum[ch];
        }
        if (ch < 0) { g_cutBucket = 0; return; }
        int b = ch * 256 + 255;
        for (; b >= ch * 256; b--) {
            acc += g_hist[b];
            if (acc >= K_TOP) break;
        }
        if (b < ch * 256) b = ch * 256;
        g_cutBucket = b;
    }
}

__global__ void k_compact() {
    int t = blockIdx.x * blockDim.x + threadIdx.x;
    if (t >= g_cnt) return;
    unsigned long long key = g_cand[t];
    if ((int)(unsigned)(key >> 48) >= g_cutBucket) {
        int pos = atomicAdd(&g_selCnt, 1);
        if (pos < SEL_MAX) g_sel[pos] = key;
    }
}

extern __shared__ unsigned long long s_keys[];
__global__ void k_sort(const float* __restrict__ boxes) {
    int t = threadIdx.x, nt = blockDim.x;
    int m = g_selCnt; if (m > SEL_MAX) m = SEL_MAX;
    int P = K_TOP;
    while (P < m) P <<= 1;

    for (int i = t; i < P; i += nt) s_keys[i] = (i < m) ? g_sel[i] : 0ull;
    __syncthreads();

    for (int k = 2; k <= P; k <<= 1) {
        for (int j = k >> 1; j > 0; j >>= 1) {
            for (int i = t; i < P; i += nt) {
                int ij = i ^ j;
                if (ij > i) {
                    unsigned long long a = s_keys[i], b = s_keys[ij];
                    bool desc = ((i & k) == 0);
                    if (desc ? (a < b) : (a > b)) { s_keys[i] = b; s_keys[ij] = a; }
                }
            }
            __syncthreads();
        }
    }

    for (int r = t; r < K_TOP; r += nt) {
        unsigned long long key = s_keys[r];
        if (key == 0ull) {
            g_val[r] = -1.0f; g_label[r] = 0;
            g_bk[r][0] = g_bk[r][1] = g_bk[r][2] = g_bk[r][3] = 0.0f;
            g_boff[r][0] = g_boff[r][1] = g_boff[r][2] = g_boff[r][3] = 0.0f;
            g_area[r] = 0.0f;
            continue;
        }
        unsigned idx = 0xFFFFFFFFu - (unsigned)(key & 0xFFFFFFFFull);
        float val = __uint_as_float((unsigned)(key >> 32));
        int bi = (int)(idx / C_CLS);
        int lb = (int)(idx % C_CLS);
        float x1 = fminf(fmaxf(boxes[bi * 4 + 0], 0.0f), IMG_W - 1.0f);
        float y1 = fminf(fmaxf(boxes[bi * 4 + 1], 0.0f), IMG_H - 1.0f);
        float x2 = fminf(fmaxf(boxes[bi * 4 + 2], 0.0f), IMG_W - 1.0f);
        float y2 = fminf(fmaxf(boxes[bi * 4 + 3], 0.0f), IMG_H - 1.0f);
        g_bk[r][0] = x1; g_bk[r][1] = y1; g_bk[r][2] = x2; g_bk[r][3] = y2;
        g_val[r] = val; g_label[r] = lb;
        float off = __fmul_rn((float)lb, CLS_OFF);
        float ox1 = __fadd_rn(x1, off), oy1 = __fadd_rn(y1, off);
        float ox2 = __fadd_rn(x2, off), oy2 = __fadd_rn(y2, off);
        g_boff[r][0] = ox1; g_boff[r][1] = oy1; g_boff[r][2] = ox2; g_boff[r][3] = oy2;
        g_area[r] = __fmul_rn(__fsub_rn(ox2, ox1), __fsub_rn(oy2, oy1));
    }
}

// suppression bitmask: mask[i][w] = bits j in [64w, 64w+64): j>i && IoU>0.5
__global__ void k_mask() {
    int colB = blockIdx.x, rowB = blockIdx.y;
    int t = threadIdx.x;  // 64 threads
    __shared__ float cb[64][4];
    __shared__ float ca[64];
    int j0 = colB * 64;
    cb[t][0] = g_boff[j0 + t][0]; cb[t][1] = g_boff[j0 + t][1];
    cb[t][2] = g_boff[j0 + t][2]; cb[t][3] = g_boff[j0 + t][3];
    ca[t] = g_area[j0 + t];
    __syncthreads();

    int i = rowB * 64 + t;
    unsigned long long w = 0ull;
    if (colB >= rowB) {
        float x1 = g_boff[i][0], y1 = g_boff[i][1], x2 = g_boff[i][2], y2 = g_boff[i][3];
        float ai = g_area[i];
        #pragma unroll 4
        for (int jj = 0; jj < 64; jj++) {
            int j = j0 + jj;
            if (j > i) {
                float iw = fmaxf(__fsub_rn(fminf(x2, cb[jj][2]), fmaxf(x1, cb[jj][0])), 0.0f);
                float ih = fmaxf(__fsub_rn(fminf(y2, cb[jj][3]), fmaxf(y1, cb[jj][1])), 0.0f);
                float inter = __fmul_rn(iw, ih);
                float denom = __fadd_rn(__fsub_rn(__fadd_rn(ai, ca[jj]), inter), 1e-9f);
                if (__fdiv_rn(inter, denom) > NMS_T) w |= (1ull << jj);
            }
        }
    }
    g_mask[(size_t)i * 64 + colB] = w;
    if (w) atomicOr(&g_rowAny[rowB], 1ull << t);
}

// sequential greedy pass over only the rows that can suppress something
__global__ void k_seq() {
    __shared__ unsigned long long removed[64];
    __shared__ int list[K_TOP];
    __shared__ int nlist;
    int t = threadIdx.x;  // 64 threads
    removed[t] = 0ull;
    if (t == 0) {
        int n = 0;
        for (int w2 = 0; w2 < 64; w2++) {
            unsigned long long bits = g_rowAny[w2];
            while (bits) {
                int b = __ffsll((long long)bits) - 1;
                bits &= bits - 1ull;
                list[n++] = w2 * 64 + b;
            }
        }
        nlist = n;
    }
    __syncthreads();
    int n = nlist;
    unsigned long long pre = n ? g_mask[(size_t)list[0] * 64 + t] : 0ull;
    for (int k = 0; k < n; k++) {
        int i = list[k];
        unsigned long long cur = pre;
        pre = (k + 1 < n) ? g_mask[(size_t)list[k + 1] * 64 + t] : 0ull;
        __syncthreads();
        if (!((removed[i >> 6] >> (i & 63)) & 1ull) && (g_val[i] > 0.0f))
            removed[t] |= cur;
    }
    __syncthreads();
    g_removed[t] = removed[t];
}

// output layout (float32, concatenated): dets[4096*5], labels[4096], keep[4096]
__global__ void k_out(float* __restrict__ out, int out_size) {
    int t = blockIdx.x * blockDim.x + threadIdx.x;
    if (t >= out_size) return;
    float v = 0.0f;
    if (t < K_TOP * 5) {
        int r = t / 5, c = t - r * 5;
        bool keep = !((g_removed[r >> 6] >> (r & 63)) & 1ull) && (g_val[r] > 0.0f);
        if (keep) v = (c < 4) ? g_bk[r][c] : g_val[r];
    } else if (t < K_TOP * 6) {
        v = (float)g_label[t - K_TOP * 5];
    } else if (t < K_TOP * 7) {
        int r = t - K_TOP * 6;
        bool keep = !((g_removed[r >> 6] >> (r & 63)) & 1ull) && (g_val[r] > 0.0f);
        v = keep ? 1.0f : 0.0f;
    }
    out[t] = v;
}

extern "C" void kernel_launch(void* const* d_in, const int* in_sizes, int n_in,
                              void* d_out, int out_size) {
    const float* x     = (const float*)d_in[0];
    const float* boxes = (const float*)d_in[1];
    float* out = (float*)d_out;

    cudaFuncSetAttribute(k_sort, cudaFuncAttributeMaxDynamicSharedMemorySize, SEL_MAX * 8);

    k_zero<<<257, 256>>>();
    k_softmax<<<N_BOX / 8, 256>>>(x);
    k_findcut<<<1, 256>>>();
    k_compact<<<CAND_MAX / 256, 256>>>();
    k_sort<<<1, 1024, SEL_MAX * 8>>>(boxes);
    dim3 gm(64, 64);
    k_mask<<<gm, 64>>>();
    k_seq<<<1, 64>>>();
    int nthr = (out_size + 255) / 256;
    k_out<<<nthr, 256>>>(out, out_size);
}

// round 7
// speedup vs baseline: 1.7134x; 1.7134x over previous
#include <cuda_runtime.h>
#include <stdint.h>

#define N_BOX 32768
#define C_CLS 81
#define K_TOP 4096
#define SCORE_T 0.05f
#define NMS_T 0.5f
#define IMG_W 1333.0f
#define IMG_H 800.0f
#define CLS_OFF 4096.0f

#define CAND_MAX (N_BOX * 20)   // provably <=19 candidates/row (probs sum to 1)
#define SEL_MAX 16384

__device__ unsigned long long g_cand[CAND_MAX];
__device__ int g_cnt;
__device__ unsigned int g_hist[65536];
__device__ int g_cutBucket;
__device__ unsigned long long g_sel[SEL_MAX];
__device__ int g_selCnt;
__device__ int g_rank[SEL_MAX];

__device__ float g_bk[K_TOP][4];
__device__ float g_boff[K_TOP][4];
__device__ float g_area[K_TOP];
__device__ float g_val[K_TOP];
__device__ int   g_label[K_TOP];

__device__ unsigned long long g_mask[K_TOP * 64];  // suppression bitmatrix (lower triangle stays 0 forever)
__device__ unsigned long long g_rowAny[64];
__device__ unsigned long long g_removed[64];

// xor-butterfly tree sum over the warp — all lanes end with identical bits
__device__ __forceinline__ float btree_add(float v) {
    #pragma unroll
    for (int o = 16; o; o >>= 1) v = __fadd_rn(v, __shfl_xor_sync(0xFFFFFFFFu, v, o));
    return v;
}

__global__ void k_zero() {
    int t = blockIdx.x * blockDim.x + threadIdx.x;
    if (t < 65536) g_hist[t] = 0u;
    if (t < SEL_MAX) g_rank[t] = 0;
    if (t < 64)    g_rowAny[t] = 0ull;
    if (t == 0) { g_cnt = 0; g_selCnt = 0; }
    if (t < K_TOP) {   // pad defaults (only visible if m < K_TOP)
        g_val[t] = -1.0f; g_label[t] = 0; g_area[t] = 0.0f;
        g_bk[t][0] = g_bk[t][1] = g_bk[t][2] = g_bk[t][3] = 0.0f;
        g_boff[t][0] = g_boff[t][1] = g_boff[t][2] = g_boff[t][3] = 0.0f;
    }
}

// one warp per row — bitwise model of the Triton/MLIR normalization emitter
// (VALIDATED in round 6: rel_err 9.3e-12 — DO NOT change any arithmetic here)
__global__ void k_softmax(const float* __restrict__ x) {
    int warp = (blockIdx.x * blockDim.x + threadIdx.x) >> 5;
    int lane = threadIdx.x & 31;
    if (warp >= N_BOX) return;
    const float* row = x + (size_t)warp * C_CLS;

    float v0 = row[lane];
    float v1 = row[lane + 32];
    float v2 = (lane < 17) ? row[lane + 64] : -1e30f;

    float m = fmaxf(fmaxf(v0, v1), v2);
    #pragma unroll
    for (int o = 16; o; o >>= 1) m = fmaxf(m, __shfl_xor_sync(0xFFFFFFFFu, m, o));

    float e0 = expf(__fsub_rn(v0, m));
    float e1 = expf(__fsub_rn(v1, m));
    float e2 = (lane < 17) ? expf(__fsub_rn(v2, m)) : 0.0f;

    float B0 = btree_add(e0);
    float B1 = btree_add(e1);
    float B2 = btree_add(e2);
    float s = __fadd_rn(__fadd_rn(B0, B2), B1);

    float p[3];
    p[0] = __fdiv_rn(e0, s); p[1] = __fdiv_rn(e1, s); p[2] = __fdiv_rn(e2, s);

    #pragma unroll
    for (int k = 0; k < 3; k++) {
        int c = lane + 32 * k;
        bool valid = (c != 0) && (c < C_CLS) && (p[k] > SCORE_T);
        unsigned bal = __ballot_sync(0xFFFFFFFFu, valid);
        int nsel = __popc(bal);
        int base = 0;
        if (lane == 0 && nsel) base = atomicAdd(&g_cnt, nsel);
        base = __shfl_sync(0xFFFFFFFFu, base, 0);
        if (valid) {
            unsigned vb = __float_as_uint(p[k]);
            int pos = base + __popc(bal & ((1u << lane) - 1u));
            unsigned idx = (unsigned)warp * C_CLS + (unsigned)c;
            g_cand[pos] = ((unsigned long long)vb << 32) | (0xFFFFFFFFu - idx);
            atomicAdd(&g_hist[vb >> 16], 1u);
        }
    }
}

__global__ void k_findcut() {
    __shared__ unsigned int csum[256];
    int t = threadIdx.x;
    unsigned int s = 0;
    #pragma unroll 8
    for (int i = 0; i < 256; i++) s += g_hist[t * 256 + i];
    csum[t] = s;
    __syncthreads();
    if (t == 0) {
        unsigned int acc = 0;
        int ch = 255;
        for (; ch >= 0; ch--) {
            if (acc + csum[ch] >= K_TOP) break;
            acc += csum[ch];
        }
        if (ch < 0) { g_cutBucket = 0; return; }
        int b = ch * 256 + 255;
        for (; b >= ch * 256; b--) {
            acc += g_hist[b];
            if (acc >= K_TOP) break;
        }
        if (b < ch * 256) b = ch * 256;
        g_cutBucket = b;
    }
}

__global__ void k_compact() {
    int t = blockIdx.x * blockDim.x + threadIdx.x;
    if (t >= g_cnt) return;
    unsigned long long key = g_cand[t];
    if ((int)(unsigned)(key >> 48) >= g_cutBucket) {
        int pos = atomicAdd(&g_selCnt, 1);
        if (pos < SEL_MAX) g_sel[pos] = key;
    }
}

// exact dense rank (descending): rank[i] = #{j : key_j > key_i}. Keys unique,
// so ranks are a permutation — replaces the single-CTA bitonic sort entirely.
__global__ void k_rank() {
    __shared__ unsigned long long tile[256];
    int m = g_selCnt; if (m > SEL_MAX) m = SEL_MAX;
    int bi = blockIdx.x, bj = blockIdx.y;
    int i0 = bi * 256, j0 = bj * 256;
    if (i0 >= m || j0 >= m) return;                 // uniform per block
    int jt = j0 + threadIdx.x;
    tile[threadIdx.x] = (jt < m) ? g_sel[jt] : 0ull; // pad keys are 0 (< any real key)
    __syncthreads();
    int i = i0 + threadIdx.x;
    if (i >= m) return;
    unsigned long long key = g_sel[i];
    int lim = m - j0; if (lim > 256) lim = 256;
    int cnt = 0;
    #pragma unroll 8
    for (int j = 0; j < lim; j++) cnt += (tile[j] > key);
    if (cnt) atomicAdd(&g_rank[i], cnt);
}

// decode each selected key straight into its final sorted slot
__global__ void k_scatter(const float* __restrict__ boxes) {
    int m = g_selCnt; if (m > SEL_MAX) m = SEL_MAX;
    int i = blockIdx.x * blockDim.x + threadIdx.x;
    if (i >= m) return;
    int r = g_rank[i];
    if (r >= K_TOP) return;
    unsigned long long key = g_sel[i];
    unsigned idx = 0xFFFFFFFFu - (unsigned)(key & 0xFFFFFFFFull);
    float val = __uint_as_float((unsigned)(key >> 32));
    int bi = (int)(idx / C_CLS);
    int lb = (int)(idx % C_CLS);
    float x1 = fminf(fmaxf(boxes[bi * 4 + 0], 0.0f), IMG_W - 1.0f);
    float y1 = fminf(fmaxf(boxes[bi * 4 + 1], 0.0f), IMG_H - 1.0f);
    float x2 = fminf(fmaxf(boxes[bi * 4 + 2], 0.0f), IMG_W - 1.0f);
    float y2 = fminf(fmaxf(boxes[bi * 4 + 3], 0.0f), IMG_H - 1.0f);
    g_bk[r][0] = x1; g_bk[r][1] = y1; g_bk[r][2] = x2; g_bk[r][3] = y2;
    g_val[r] = val; g_label[r] = lb;
    float off = __fmul_rn((float)lb, CLS_OFF);
    float ox1 = __fadd_rn(x1, off), oy1 = __fadd_rn(y1, off);
    float ox2 = __fadd_rn(x2, off), oy2 = __fadd_rn(y2, off);
    g_boff[r][0] = ox1; g_boff[r][1] = oy1; g_boff[r][2] = ox2; g_boff[r][3] = oy2;
    g_area[r] = __fmul_rn(__fsub_rn(ox2, ox1), __fsub_rn(oy2, oy1));
}

// suppression bitmask over the upper triangle only (lower-triangle words are
// never written and remain the module-init zeros — k_seq reads them as 0)
__global__ void k_mask() {
    int q = blockIdx.x;
    // decode q -> (rowB <= colB): colB = triangular root, rowB = q - colB(colB+1)/2
    int colB = (int)((sqrtf(8.0f * (float)q + 1.0f) - 1.0f) * 0.5f);
    while ((colB + 1) * (colB + 2) / 2 <= q) colB++;
    while (colB * (colB + 1) / 2 > q) colB--;
    int rowB = q - colB * (colB + 1) / 2;

    int t = threadIdx.x;  // 64 threads
    __shared__ float cb[64][4];
    __shared__ float ca[64];
    int j0 = colB * 64;
    cb[t][0] = g_boff[j0 + t][0]; cb[t][1] = g_boff[j0 + t][1];
    cb[t][2] = g_boff[j0 + t][2]; cb[t][3] = g_boff[j0 + t][3];
    ca[t] = g_area[j0 + t];
    __syncthreads();

    int i = rowB * 64 + t;
    unsigned long long w = 0ull;
    {
        float x1 = g_boff[i][0], y1 = g_boff[i][1], x2 = g_boff[i][2], y2 = g_boff[i][3];
        float ai = g_area[i];
        #pragma unroll 4
        for (int jj = 0; jj < 64; jj++) {
            int j = j0 + jj;
            if (j > i) {
                float iw = fmaxf(__fsub_rn(fminf(x2, cb[jj][2]), fmaxf(x1, cb[jj][0])), 0.0f);
                float ih = fmaxf(__fsub_rn(fminf(y2, cb[jj][3]), fmaxf(y1, cb[jj][1])), 0.0f);
                float inter = __fmul_rn(iw, ih);
                float denom = __fadd_rn(__fsub_rn(__fadd_rn(ai, ca[jj]), inter), 1e-9f);
                if (__fdiv_rn(inter, denom) > NMS_T) w |= (1ull << jj);
            }
        }
    }
    g_mask[(size_t)i * 64 + colB] = w;
    if (w) atomicOr(&g_rowAny[rowB], 1ull << t);
}

// sequential greedy pass over only the rows that can suppress something
__global__ void k_seq() {
    __shared__ unsigned long long removed[64];
    __shared__ int list[K_TOP];
    __shared__ int nlist;
    int t = threadIdx.x;  // 64 threads
    removed[t] = 0ull;
    if (t == 0) {
        int n = 0;
        for (int w2 = 0; w2 < 64; w2++) {
            unsigned long long bits = g_rowAny[w2];
            while (bits) {
                int b = __ffsll((long long)bits) - 1;
                bits &= bits - 1ull;
                list[n++] = w2 * 64 + b;
            }
        }
        nlist = n;
    }
    __syncthreads();
    int n = nlist;
    unsigned long long pre = n ? g_mask[(size_t)list[0] * 64 + t] : 0ull;
    for (int k = 0; k < n; k++) {
        int i = list[k];
        unsigned long long cur = pre;
        pre = (k + 1 < n) ? g_mask[(size_t)list[k + 1] * 64 + t] : 0ull;
        __syncthreads();
        if (!((removed[i >> 6] >> (i & 63)) & 1ull) && (g_val[i] > 0.0f))
            removed[t] |= cur;
    }
    __syncthreads();
    g_removed[t] = removed[t];
}

// output layout (float32, concatenated): dets[4096*5], labels[4096], keep[4096]
__global__ void k_out(float* __restrict__ out, int out_size) {
    int t = blockIdx.x * blockDim.x + threadIdx.x;
    if (t >= out_size) return;
    float v = 0.0f;
    if (t < K_TOP * 5) {
        int r = t / 5, c = t - r * 5;
        bool keep = !((g_removed[r >> 6] >> (r & 63)) & 1ull) && (g_val[r] > 0.0f);
        if (keep) v = (c < 4) ? g_bk[r][c] : g_val[r];
    } else if (t < K_TOP * 6) {
        v = (float)g_label[t - K_TOP * 5];
    } else if (t < K_TOP * 7) {
        int r = t - K_TOP * 6;
        bool keep = !((g_removed[r >> 6] >> (r & 63)) & 1ull) && (g_val[r] > 0.0f);
        v = keep ? 1.0f : 0.0f;
    }
    out[t] = v;
}

extern "C" void kernel_launch(void* const* d_in, const int* in_sizes, int n_in,
                              void* d_out, int out_size) {
    const float* x     = (const float*)d_in[0];
    const float* boxes = (const float*)d_in[1];
    float* out = (float*)d_out;

    k_zero<<<257, 256>>>();
    k_softmax<<<N_BOX / 8, 256>>>(x);
    k_findcut<<<1, 256>>>();
    k_compact<<<CAND_MAX / 256, 256>>>();
    dim3 gr(SEL_MAX / 256, SEL_MAX / 256);
    k_rank<<<gr, 256>>>();
    k_scatter<<<SEL_MAX / 256, 256>>>(boxes);
    k_mask<<<65 * 64 / 2, 64>>>();
    k_seq<<<1, 64>>>();
    int nthr = (out_size + 255) / 256;
    k_out<<<nthr, 256>>>(out, out_size);
}